// round 10
// baseline (speedup 1.0000x reference)
#include <cuda_runtime.h>
#include <cuda_bf16.h>
#include <cstdint>

// Problem constants
#define PB 8
#define PS 4096
#define PD 768
#define PN 64
#define D4 (PD / 4)            // 192 float4 per token row
#define NSEG (PB * PN)         // 512 segments
#define CH 64                  // tokens per chunk-block
#define NCHUNK (PS / CH)       // 64 chunks per batch
#define OUT_VEC_ELEMS ((size_t)PB * 2 * PN * PD)   // 786432

// Direct per-segment results (only written when a segment fits in one chunk)
__device__ float g_sums[NSEG * PD];
__device__ float g_cnts[NSEG * PD];
// Boundary partials: [b][chunk][2][D].  slot 0 = run extending left of chunk
// (incl. full-chunk middle runs), slot 1 = run extending right only.
__device__ float g_psum[PB * NCHUNK * 2 * PD];
__device__ float g_pcnt[PB * NCHUNK * 2 * PD];

// cross-block progress counters (zero-init; reset to 0 by last user each call)
__device__ int g_done[PB];
__device__ int g_fin[PB];

// ---------------------------------------------------------------------------
// cheap 2-warp shuffle prefix scan of this batch's 64 lengths into s_ends
// ---------------------------------------------------------------------------
__device__ __forceinline__ void scan_ends(const int* __restrict__ lens, int b,
                                          int tid, int* s_ends, int* s_w0tot) {
    if (tid < PN) {
        const int lane = tid & 31;
        int x = lens[b * PN + tid];
        #pragma unroll
        for (int off = 1; off < 32; off <<= 1) {
            int y = __shfl_up_sync(0xFFFFFFFFu, x, off);
            if (lane >= off) x += y;
        }
        if (tid == 31) *s_w0tot = x;
        s_ends[tid] = x;          // warp-local inclusive scan
    }
    __syncthreads();
    if (tid >= 32 && tid < PN) s_ends[tid] += *s_w0tot;
    __syncthreads();
}

// ---------------------------------------------------------------------------
// Single fused kernel: balanced accumulate (one block per 64-token chunk)
// + rep gather + device-side sync + per-segment finalize.
// ---------------------------------------------------------------------------
__global__ __launch_bounds__(192, 4) void fused_kernel(
    const float* __restrict__ wv,
    const int* __restrict__ lens,
    const int* __restrict__ ids,
    const float* __restrict__ rmask,
    const float* __restrict__ lmask,
    float* __restrict__ out)
{
    __shared__ int s_ends[PN];
    __shared__ int s_w0tot;
    const int blk = blockIdx.x;
    const int b = blk >> 6;              // blk / NCHUNK
    const int c = blk & (NCHUNK - 1);
    const int tid = threadIdx.x;

    scan_ends(lens, b, tid, s_ends, &s_w0tot);

    // ---- rep-token gather (independent work; overlaps the reduction) ----
    {
        const int n = c;                 // NCHUNK == PN
        const int id = ids[b * PN + n];
        const float rm = rmask[b * PN + n];
        float4 v = reinterpret_cast<const float4*>(wv)[((size_t)b * PS + id) * D4 + tid];
        v.x *= rm; v.y *= rm; v.z *= rm; v.w *= rm;
        reinterpret_cast<float4*>(out)[((size_t)b * (2 * PN) + n) * D4 + tid] = v;
        if (tid == 0) {
            float* outm = out + OUT_VEC_ELEMS;
            outm[b * (2 * PN) + n]      = rm;
            outm[b * (2 * PN) + PN + n] = lmask[b * PN + n];
        }
    }

    const int t0 = c * CH;
    const int t1 = t0 + CH;

    // first segment containing token t0
    int seg = 0;
    while (s_ends[seg] <= t0) seg++;

    const float4* base = reinterpret_cast<const float4*>(wv) +
                         (size_t)b * PS * D4 + tid;

    int t = t0;
    while (t < t1) {
        const int re = min(t1, s_ends[seg]);

        float4 acc = make_float4(0.f, 0.f, 0.f, 0.f);
        float4 cnt = make_float4(0.f, 0.f, 0.f, 0.f);

        int k = t;
        for (; k + 4 <= re; k += 4) {
            float4 v0 = base[(size_t)(k + 0) * D4];
            float4 v1 = base[(size_t)(k + 1) * D4];
            float4 v2 = base[(size_t)(k + 2) * D4];
            float4 v3 = base[(size_t)(k + 3) * D4];
            acc.x += v0.x + v1.x + v2.x + v3.x;
            acc.y += v0.y + v1.y + v2.y + v3.y;
            acc.z += v0.z + v1.z + v2.z + v3.z;
            acc.w += v0.w + v1.w + v2.w + v3.w;
            cnt.x += (v0.x != 0.f) + (v1.x != 0.f) + (v2.x != 0.f) + (v3.x != 0.f);
            cnt.y += (v0.y != 0.f) + (v1.y != 0.f) + (v2.y != 0.f) + (v3.y != 0.f);
            cnt.z += (v0.z != 0.f) + (v1.z != 0.f) + (v2.z != 0.f) + (v3.z != 0.f);
            cnt.w += (v0.w != 0.f) + (v1.w != 0.f) + (v2.w != 0.f) + (v3.w != 0.f);
        }
        for (; k < re; k++) {
            float4 v = base[(size_t)k * D4];
            acc.x += v.x; acc.y += v.y; acc.z += v.z; acc.w += v.w;
            cnt.x += (v.x != 0.f);
            cnt.y += (v.y != 0.f);
            cnt.z += (v.z != 0.f);
            cnt.w += (v.w != 0.f);
        }

        const int seg_start = seg ? s_ends[seg - 1] : 0;
        const bool ext_l = (seg_start < t0);
        const bool ext_r = (s_ends[seg] > t1);

        int slot;
        if (ext_l)      slot = (NSEG + (b * NCHUNK + c) * 2 + 0);
        else if (ext_r) slot = (NSEG + (b * NCHUNK + c) * 2 + 1);
        else            slot = (b * PN + seg);

        float4* sp = (slot < NSEG)
            ? reinterpret_cast<float4*>(g_sums) + slot * D4 + tid
            : reinterpret_cast<float4*>(g_psum) + (slot - NSEG) * D4 + tid;
        float4* cp = (slot < NSEG)
            ? reinterpret_cast<float4*>(g_cnts) + slot * D4 + tid
            : reinterpret_cast<float4*>(g_pcnt) + (slot - NSEG) * D4 + tid;
        *sp = acc;
        *cp = cnt;

        t = re;
        while (t < t1 && s_ends[seg] <= t) seg++;
    }

    // ---- publish completion of this chunk's partials ----
    __threadfence();
    __syncthreads();
    if (tid == 0) {
        atomicAdd(&g_done[b], 1);
        // spin until all 64 chunks of this batch have flushed
        while (atomicAdd(&g_done[b], 0) < NCHUNK) __nanosleep(64);
        // finalize-arrival bookkeeping; last arriver resets counters for the
        // next (graph-replayed) call.
        int old = atomicAdd(&g_fin[b], 1);
        if (old == NCHUNK - 1) {
            g_done[b] = 0;
            g_fin[b] = 0;
            __threadfence();
        }
    }
    __syncthreads();
    __threadfence();   // acquire: partials of all chunks now visible

    // ---- finalize segment n = c of batch b (bounds already in s_ends) ----
    {
        const int n = c;
        const int start = n ? s_ends[n - 1] : 0;
        const int end   = s_ends[n];

        float4 s  = make_float4(0.f, 0.f, 0.f, 0.f);
        float4 cc = make_float4(0.f, 0.f, 0.f, 0.f);

        if (end > start) {
            const int c0 = start >> 6;
            const int c1 = (end - 1) >> 6;
            if (c0 == c1) {
                s  = reinterpret_cast<const float4*>(g_sums)[(b * PN + n) * D4 + tid];
                cc = reinterpret_cast<const float4*>(g_cnts)[(b * PN + n) * D4 + tid];
            } else {
                const float4* ps = reinterpret_cast<const float4*>(g_psum);
                const float4* pc = reinterpret_cast<const float4*>(g_pcnt);
                {
                    float4 a = ps[((b * NCHUNK + c0) * 2 + 1) * D4 + tid];
                    float4 d = pc[((b * NCHUNK + c0) * 2 + 1) * D4 + tid];
                    s.x += a.x; s.y += a.y; s.z += a.z; s.w += a.w;
                    cc.x += d.x; cc.y += d.y; cc.z += d.z; cc.w += d.w;
                }
                for (int cj = c0 + 1; cj <= c1; cj++) {
                    float4 a = ps[((b * NCHUNK + cj) * 2 + 0) * D4 + tid];
                    float4 d = pc[((b * NCHUNK + cj) * 2 + 0) * D4 + tid];
                    s.x += a.x; s.y += a.y; s.z += a.z; s.w += a.w;
                    cc.x += d.x; cc.y += d.y; cc.z += d.z; cc.w += d.w;
                }
            }
        }

        // block-reduce total nonzero count (for all_zero fallback)
        float tot = cc.x + cc.y + cc.z + cc.w;
        #pragma unroll
        for (int off = 16; off > 0; off >>= 1)
            tot += __shfl_down_sync(0xFFFFFFFFu, tot, off);
        __shared__ float warp_tot[6];
        const int wid = tid >> 5, lid = tid & 31;
        if (lid == 0) warp_tot[wid] = tot;
        __syncthreads();
        const float total = warp_tot[0] + warp_tot[1] + warp_tot[2] +
                            warp_tot[3] + warp_tot[4] + warp_tot[5];

        float4 mean;
        mean.x = s.x / fmaxf(cc.x, 1.f);
        mean.y = s.y / fmaxf(cc.y, 1.f);
        mean.z = s.z / fmaxf(cc.z, 1.f);
        mean.w = s.w / fmaxf(cc.w, 1.f);
        if (total == 0.f)
            mean = reinterpret_cast<const float4*>(wv)[tid];   // wv[0,0,:]

        const float lm = lmask[b * PN + n];
        float4 om;
        om.x = mean.x * lm; om.y = mean.y * lm;
        om.z = mean.z * lm; om.w = mean.w * lm;
        reinterpret_cast<float4*>(out)[((size_t)b * (2 * PN) + PN + n) * D4 + tid] = om;
    }
}

// ---------------------------------------------------------------------------
extern "C" void kernel_launch(void* const* d_in, const int* in_sizes, int n_in,
                              void* d_out, int out_size) {
    const float* wv    = (const float*)d_in[0];  // [B,S,D] f32
    const int*   ids   = (const int*)d_in[1];    // [B,N] i32
    const float* rmask = (const float*)d_in[2];  // [B,N] f32
    const int*   lens  = (const int*)d_in[3];    // [B,N] i32
    const float* lmask = (const float*)d_in[4];  // [B,N] f32
    float* out = (float*)d_out;

    fused_kernel<<<PB * NCHUNK, 192>>>(wv, lens, ids, rmask, lmask, out);
}

// round 12
// speedup vs baseline: 1.0012x; 1.0012x over previous
#include <cuda_runtime.h>
#include <cuda_bf16.h>
#include <cstdint>

// Problem constants
#define PB 8
#define PS 4096
#define PD 768
#define PN 64
#define D4 (PD / 4)            // 192 float4 per token row
#define NSEG (PB * PN)         // 512 segments
#define CH 64                  // tokens per chunk-block
#define NCHUNK (PS / CH)       // 64 chunks per batch
#define OUT_VEC_ELEMS ((size_t)PB * 2 * PN * PD)   // 786432

// Direct per-segment results (only written when a segment fits in one chunk)
__device__ float g_sums[NSEG * PD];
__device__ float g_cnts[NSEG * PD];
// Boundary partials: [b][chunk][2][D].  slot 0 = run extending left of chunk
// (incl. full-chunk middle runs), slot 1 = run extending right only.
__device__ float g_psum[PB * NCHUNK * 2 * PD];
__device__ float g_pcnt[PB * NCHUNK * 2 * PD];

// cross-block progress counters (zero-init; reset to 0 by last user each call)
__device__ int g_done[PB];
__device__ int g_fin[PB];

// ---------------------------------------------------------------------------
// cheap 2-warp shuffle prefix scan of this batch's 64 lengths into s_ends
// ---------------------------------------------------------------------------
__device__ __forceinline__ void scan_ends(const int* __restrict__ lens, int b,
                                          int tid, int* s_ends, int* s_w0tot) {
    if (tid < PN) {
        const int lane = tid & 31;
        int x = lens[b * PN + tid];
        #pragma unroll
        for (int off = 1; off < 32; off <<= 1) {
            int y = __shfl_up_sync(0xFFFFFFFFu, x, off);
            if (lane >= off) x += y;
        }
        if (tid == 31) *s_w0tot = x;
        s_ends[tid] = x;          // warp-local inclusive scan
    }
    __syncthreads();
    if (tid >= 32 && tid < PN) s_ends[tid] += *s_w0tot;
    __syncthreads();
}

// ---------------------------------------------------------------------------
// Single fused kernel: balanced accumulate (one block per 64-token chunk)
// + rep gather + device-side sync + per-segment finalize.
// Count trick: track min|v| per lane; zero-free run (the ~always case)
// means per-dim nonzero count == run length. Rare slow path recounts.
// ---------------------------------------------------------------------------
__global__ __launch_bounds__(192, 4) void fused_kernel(
    const float* __restrict__ wv,
    const int* __restrict__ lens,
    const int* __restrict__ ids,
    const float* __restrict__ rmask,
    const float* __restrict__ lmask,
    float* __restrict__ out)
{
    __shared__ int s_ends[PN];
    __shared__ int s_w0tot;
    const int blk = blockIdx.x;
    const int b = blk >> 6;              // blk / NCHUNK
    const int c = blk & (NCHUNK - 1);
    const int tid = threadIdx.x;

    scan_ends(lens, b, tid, s_ends, &s_w0tot);

    // ---- rep-token gather (independent work; overlaps the reduction) ----
    {
        const int n = c;                 // NCHUNK == PN
        const int id = ids[b * PN + n];
        const float rm = rmask[b * PN + n];
        float4 v = reinterpret_cast<const float4*>(wv)[((size_t)b * PS + id) * D4 + tid];
        v.x *= rm; v.y *= rm; v.z *= rm; v.w *= rm;
        reinterpret_cast<float4*>(out)[((size_t)b * (2 * PN) + n) * D4 + tid] = v;
        if (tid == 0) {
            float* outm = out + OUT_VEC_ELEMS;
            outm[b * (2 * PN) + n]      = rm;
            outm[b * (2 * PN) + PN + n] = lmask[b * PN + n];
        }
    }

    const int t0 = c * CH;
    const int t1 = t0 + CH;

    // first segment containing token t0
    int seg = 0;
    while (s_ends[seg] <= t0) seg++;

    const float4* base = reinterpret_cast<const float4*>(wv) +
                         (size_t)b * PS * D4 + tid;

    int t = t0;
    while (t < t1) {
        const int re = min(t1, s_ends[seg]);

        float4 acc = make_float4(0.f, 0.f, 0.f, 0.f);
        float4 mn  = make_float4(1.f, 1.f, 1.f, 1.f);   // min |v| per lane

        int k = t;
        for (; k + 4 <= re; k += 4) {
            float4 v0 = base[(size_t)(k + 0) * D4];
            float4 v1 = base[(size_t)(k + 1) * D4];
            float4 v2 = base[(size_t)(k + 2) * D4];
            float4 v3 = base[(size_t)(k + 3) * D4];
            acc.x += v0.x + v1.x + v2.x + v3.x;
            acc.y += v0.y + v1.y + v2.y + v3.y;
            acc.z += v0.z + v1.z + v2.z + v3.z;
            acc.w += v0.w + v1.w + v2.w + v3.w;
            mn.x = fminf(fminf(mn.x, fabsf(v0.x)), fminf(fabsf(v1.x), fminf(fabsf(v2.x), fabsf(v3.x))));
            mn.y = fminf(fminf(mn.y, fabsf(v0.y)), fminf(fabsf(v1.y), fminf(fabsf(v2.y), fabsf(v3.y))));
            mn.z = fminf(fminf(mn.z, fabsf(v0.z)), fminf(fabsf(v1.z), fminf(fabsf(v2.z), fabsf(v3.z))));
            mn.w = fminf(fminf(mn.w, fabsf(v0.w)), fminf(fabsf(v1.w), fminf(fabsf(v2.w), fabsf(v3.w))));
        }
        for (; k < re; k++) {
            float4 v = base[(size_t)k * D4];
            acc.x += v.x; acc.y += v.y; acc.z += v.z; acc.w += v.w;
            mn.x = fminf(mn.x, fabsf(v.x));
            mn.y = fminf(mn.y, fabsf(v.y));
            mn.z = fminf(mn.z, fabsf(v.z));
            mn.w = fminf(mn.w, fabsf(v.w));
        }

        const float rl = (float)(re - t);
        float4 cnt = make_float4(rl, rl, rl, rl);
        if (!(mn.x > 0.f && mn.y > 0.f && mn.z > 0.f && mn.w > 0.f)) {
            // rare slow path: some lane saw an exact/flushed zero (or NaN) —
            // recount exactly with the reference's (v != 0) semantics.
            cnt = make_float4(0.f, 0.f, 0.f, 0.f);
            for (int j = t; j < re; j++) {
                float4 v = base[(size_t)j * D4];
                cnt.x += (v.x != 0.f);
                cnt.y += (v.y != 0.f);
                cnt.z += (v.z != 0.f);
                cnt.w += (v.w != 0.f);
            }
        }

        const int seg_start = seg ? s_ends[seg - 1] : 0;
        const bool ext_l = (seg_start < t0);
        const bool ext_r = (s_ends[seg] > t1);

        int slot;
        if (ext_l)      slot = (NSEG + (b * NCHUNK + c) * 2 + 0);
        else if (ext_r) slot = (NSEG + (b * NCHUNK + c) * 2 + 1);
        else            slot = (b * PN + seg);

        float4* sp = (slot < NSEG)
            ? reinterpret_cast<float4*>(g_sums) + slot * D4 + tid
            : reinterpret_cast<float4*>(g_psum) + (slot - NSEG) * D4 + tid;
        float4* cp = (slot < NSEG)
            ? reinterpret_cast<float4*>(g_cnts) + slot * D4 + tid
            : reinterpret_cast<float4*>(g_pcnt) + (slot - NSEG) * D4 + tid;
        *sp = acc;
        *cp = cnt;

        t = re;
        while (t < t1 && s_ends[seg] <= t) seg++;
    }

    // ---- publish completion of this chunk's partials ----
    __threadfence();
    __syncthreads();
    if (tid == 0) {
        atomicAdd(&g_done[b], 1);
        // spin until all 64 chunks of this batch have flushed
        while (atomicAdd(&g_done[b], 0) < NCHUNK) __nanosleep(64);
        // finalize-arrival bookkeeping; last arriver resets counters for the
        // next (graph-replayed) call.
        int old = atomicAdd(&g_fin[b], 1);
        if (old == NCHUNK - 1) {
            g_done[b] = 0;
            g_fin[b] = 0;
            __threadfence();
        }
    }
    __syncthreads();
    __threadfence();   // acquire: partials of all chunks now visible

    // ---- finalize segment n = c of batch b (bounds already in s_ends) ----
    {
        const int n = c;
        const int start = n ? s_ends[n - 1] : 0;
        const int end   = s_ends[n];

        float4 s  = make_float4(0.f, 0.f, 0.f, 0.f);
        float4 cc = make_float4(0.f, 0.f, 0.f, 0.f);

        if (end > start) {
            const int c0 = start >> 6;
            const int c1 = (end - 1) >> 6;
            if (c0 == c1) {
                s  = reinterpret_cast<const float4*>(g_sums)[(b * PN + n) * D4 + tid];
                cc = reinterpret_cast<const float4*>(g_cnts)[(b * PN + n) * D4 + tid];
            } else {
                const float4* ps = reinterpret_cast<const float4*>(g_psum);
                const float4* pc = reinterpret_cast<const float4*>(g_pcnt);
                {
                    float4 a = ps[((b * NCHUNK + c0) * 2 + 1) * D4 + tid];
                    float4 d = pc[((b * NCHUNK + c0) * 2 + 1) * D4 + tid];
                    s.x += a.x; s.y += a.y; s.z += a.z; s.w += a.w;
                    cc.x += d.x; cc.y += d.y; cc.z += d.z; cc.w += d.w;
                }
                for (int cj = c0 + 1; cj <= c1; cj++) {
                    float4 a = ps[((b * NCHUNK + cj) * 2 + 0) * D4 + tid];
                    float4 d = pc[((b * NCHUNK + cj) * 2 + 0) * D4 + tid];
                    s.x += a.x; s.y += a.y; s.z += a.z; s.w += a.w;
                    cc.x += d.x; cc.y += d.y; cc.z += d.z; cc.w += d.w;
                }
            }
        }

        // block-reduce total nonzero count (for all_zero fallback)
        float tot = cc.x + cc.y + cc.z + cc.w;
        #pragma unroll
        for (int off = 16; off > 0; off >>= 1)
            tot += __shfl_down_sync(0xFFFFFFFFu, tot, off);
        __shared__ float warp_tot[6];
        const int wid = tid >> 5, lid = tid & 31;
        if (lid == 0) warp_tot[wid] = tot;
        __syncthreads();
        const float total = warp_tot[0] + warp_tot[1] + warp_tot[2] +
                            warp_tot[3] + warp_tot[4] + warp_tot[5];

        float4 mean;
        mean.x = s.x / fmaxf(cc.x, 1.f);
        mean.y = s.y / fmaxf(cc.y, 1.f);
        mean.z = s.z / fmaxf(cc.z, 1.f);
        mean.w = s.w / fmaxf(cc.w, 1.f);
        if (total == 0.f)
            mean = reinterpret_cast<const float4*>(wv)[tid];   // wv[0,0,:]

        const float lm = lmask[b * PN + n];
        float4 om;
        om.x = mean.x * lm; om.y = mean.y * lm;
        om.z = mean.z * lm; om.w = mean.w * lm;
        reinterpret_cast<float4*>(out)[((size_t)b * (2 * PN) + PN + n) * D4 + tid] = om;
    }
}

// ---------------------------------------------------------------------------
extern "C" void kernel_launch(void* const* d_in, const int* in_sizes, int n_in,
                              void* d_out, int out_size) {
    const float* wv    = (const float*)d_in[0];  // [B,S,D] f32
    const int*   ids   = (const int*)d_in[1];    // [B,N] i32
    const float* rmask = (const float*)d_in[2];  // [B,N] f32
    const int*   lens  = (const int*)d_in[3];    // [B,N] i32
    const float* lmask = (const float*)d_in[4];  // [B,N] f32
    float* out = (float*)d_out;

    fused_kernel<<<PB * NCHUNK, 192>>>(wv, lens, ids, rmask, lmask, out);
}

// round 13
// speedup vs baseline: 1.0932x; 1.0920x over previous
#include <cuda_runtime.h>
#include <cuda_bf16.h>
#include <cstdint>

// Problem constants
#define PB 8
#define PS 4096
#define PD 768
#define PN 64
#define D4 (PD / 4)            // 192 float4 per token row
#define NSEG (PB * PN)         // 512 segments
#define CH 64                  // tokens per chunk-block
#define NCHUNK (PS / CH)       // 64 chunks per batch
#define OUT_VEC_ELEMS ((size_t)PB * 2 * PN * PD)   // 786432
#define PF 8                   // prefetch ring depth

// Direct per-segment results (only written when a segment fits in one chunk)
__device__ float g_sums[NSEG * PD];
__device__ float g_cnts[NSEG * PD];
// Boundary partials: [b][chunk][2][D].  slot 0 = run extending left of chunk
// (incl. full-chunk middle runs), slot 1 = run extending right only.
__device__ float g_psum[PB * NCHUNK * 2 * PD];
__device__ float g_pcnt[PB * NCHUNK * 2 * PD];

// cross-block progress counters (zero-init; reset to 0 by last user each call)
__device__ int g_done[PB];
__device__ int g_fin[PB];

// ---------------------------------------------------------------------------
// cheap 2-warp shuffle prefix scan of this batch's 64 lengths into s_ends
// ---------------------------------------------------------------------------
__device__ __forceinline__ void scan_ends(const int* __restrict__ lens, int b,
                                          int tid, int* s_ends, int* s_w0tot) {
    if (tid < PN) {
        const int lane = tid & 31;
        int x = lens[b * PN + tid];
        #pragma unroll
        for (int off = 1; off < 32; off <<= 1) {
            int y = __shfl_up_sync(0xFFFFFFFFu, x, off);
            if (lane >= off) x += y;
        }
        if (tid == 31) *s_w0tot = x;
        s_ends[tid] = x;          // warp-local inclusive scan
    }
    __syncthreads();
    if (tid >= 32 && tid < PN) s_ends[tid] += *s_w0tot;
    __syncthreads();
}

// ---------------------------------------------------------------------------
// Single fused kernel: balanced accumulate (one block per 64-token chunk)
// + rep gather + device-side sync + per-segment finalize.
// The token loop is software-pipelined with an 8-deep register ring so the
// load stream never drains at run boundaries (sustained per-thread MLP ~ 8).
// ---------------------------------------------------------------------------
__global__ __launch_bounds__(192, 4) void fused_kernel(
    const float* __restrict__ wv,
    const int* __restrict__ lens,
    const int* __restrict__ ids,
    const float* __restrict__ rmask,
    const float* __restrict__ lmask,
    float* __restrict__ out)
{
    __shared__ int s_ends[PN];
    __shared__ int s_w0tot;
    const int blk = blockIdx.x;
    const int b = blk >> 6;              // blk / NCHUNK
    const int c = blk & (NCHUNK - 1);
    const int tid = threadIdx.x;

    scan_ends(lens, b, tid, s_ends, &s_w0tot);

    const int t0 = c * CH;
    const int t1 = t0 + CH;

    const float4* base = reinterpret_cast<const float4*>(wv) +
                         (size_t)b * PS * D4 + tid;

    // ---- prime the load ring for tokens t0 .. t0+PF-1 ----
    float4 buf[PF];
    #pragma unroll
    for (int j = 0; j < PF; j++)
        buf[j] = base[(size_t)(t0 + j) * D4];

    // ---- rep-token gather (independent; issued while ring loads fly) ----
    {
        const int n = c;                 // NCHUNK == PN
        const int id = ids[b * PN + n];
        const float rm = rmask[b * PN + n];
        float4 v = reinterpret_cast<const float4*>(wv)[((size_t)b * PS + id) * D4 + tid];
        v.x *= rm; v.y *= rm; v.z *= rm; v.w *= rm;
        reinterpret_cast<float4*>(out)[((size_t)b * (2 * PN) + n) * D4 + tid] = v;
        if (tid == 0) {
            float* outm = out + OUT_VEC_ELEMS;
            outm[b * (2 * PN) + n]      = rm;
            outm[b * (2 * PN) + PN + n] = lmask[b * PN + n];
        }
    }

    // first segment containing token t0
    int seg = 0;
    while (s_ends[seg] <= t0) seg++;
    int nend = s_ends[seg];

    float4 acc = make_float4(0.f, 0.f, 0.f, 0.f);
    float4 mn  = make_float4(1.f, 1.f, 1.f, 1.f);
    int rs = t0;                         // current run start

    for (int g = 0; g < CH / PF; g++) {
        const bool more = (g < CH / PF - 1);
        #pragma unroll
        for (int j = 0; j < PF; j++) {
            const int k = t0 + g * PF + j;
            const float4 v = buf[j];
            if (more) buf[j] = base[(size_t)(k + PF) * D4];   // refill ring

            acc.x += v.x; acc.y += v.y; acc.z += v.z; acc.w += v.w;
            mn.x = fminf(mn.x, fabsf(v.x));
            mn.y = fminf(mn.y, fabsf(v.y));
            mn.z = fminf(mn.z, fabsf(v.z));
            mn.w = fminf(mn.w, fabsf(v.w));

            if (k + 1 == nend) {
                // ---- flush run [rs, k+1) ----
                const int ke = k + 1;
                const float rl = (float)(ke - rs);
                float4 cnt = make_float4(rl, rl, rl, rl);
                if (!(mn.x > 0.f && mn.y > 0.f && mn.z > 0.f && mn.w > 0.f)) {
                    cnt = make_float4(0.f, 0.f, 0.f, 0.f);
                    for (int q = rs; q < ke; q++) {
                        float4 w = base[(size_t)q * D4];
                        cnt.x += (w.x != 0.f);
                        cnt.y += (w.y != 0.f);
                        cnt.z += (w.z != 0.f);
                        cnt.w += (w.w != 0.f);
                    }
                }
                const int seg_start = seg ? s_ends[seg - 1] : 0;
                int slot;
                if (seg_start < t0) slot = NSEG + (b * NCHUNK + c) * 2 + 0;
                else                slot = b * PN + seg;
                float4* sp = (slot < NSEG)
                    ? reinterpret_cast<float4*>(g_sums) + slot * D4 + tid
                    : reinterpret_cast<float4*>(g_psum) + (slot - NSEG) * D4 + tid;
                float4* cp = (slot < NSEG)
                    ? reinterpret_cast<float4*>(g_cnts) + slot * D4 + tid
                    : reinterpret_cast<float4*>(g_pcnt) + (slot - NSEG) * D4 + tid;
                *sp = acc;
                *cp = cnt;

                acc = make_float4(0.f, 0.f, 0.f, 0.f);
                mn  = make_float4(1.f, 1.f, 1.f, 1.f);
                rs = ke;
                if (ke < t1) {
                    do { seg++; } while (seg < PN && s_ends[seg] == ke);
                    nend = s_ends[seg];
                }
            }
        }
    }

    // ---- trailing run extending past the chunk's right edge ----
    if (rs < t1) {
        const float rl = (float)(t1 - rs);
        float4 cnt = make_float4(rl, rl, rl, rl);
        if (!(mn.x > 0.f && mn.y > 0.f && mn.z > 0.f && mn.w > 0.f)) {
            cnt = make_float4(0.f, 0.f, 0.f, 0.f);
            for (int q = rs; q < t1; q++) {
                float4 w = base[(size_t)q * D4];
                cnt.x += (w.x != 0.f);
                cnt.y += (w.y != 0.f);
                cnt.z += (w.z != 0.f);
                cnt.w += (w.w != 0.f);
            }
        }
        const int seg_start = seg ? s_ends[seg - 1] : 0;
        int slot;
        if (seg_start < t0) slot = NSEG + (b * NCHUNK + c) * 2 + 0;  // spans whole chunk
        else                slot = NSEG + (b * NCHUNK + c) * 2 + 1;  // starts here, extends right
        float4* sp = (slot < NSEG)
            ? reinterpret_cast<float4*>(g_sums) + slot * D4 + tid
            : reinterpret_cast<float4*>(g_psum) + (slot - NSEG) * D4 + tid;
        float4* cp = (slot < NSEG)
            ? reinterpret_cast<float4*>(g_cnts) + slot * D4 + tid
            : reinterpret_cast<float4*>(g_pcnt) + (slot - NSEG) * D4 + tid;
        *sp = acc;
        *cp = cnt;
    }

    // ---- publish completion of this chunk's partials ----
    __threadfence();
    __syncthreads();
    if (tid == 0) {
        atomicAdd(&g_done[b], 1);
        while (atomicAdd(&g_done[b], 0) < NCHUNK) __nanosleep(64);
        int old = atomicAdd(&g_fin[b], 1);
        if (old == NCHUNK - 1) {          // last arriver resets for next replay
            g_done[b] = 0;
            g_fin[b] = 0;
            __threadfence();
        }
    }
    __syncthreads();
    __threadfence();   // acquire: partials of all chunks now visible

    // ---- finalize segment n = c of batch b (bounds already in s_ends) ----
    {
        const int n = c;
        const int start = n ? s_ends[n - 1] : 0;
        const int end   = s_ends[n];

        float4 s  = make_float4(0.f, 0.f, 0.f, 0.f);
        float4 cc = make_float4(0.f, 0.f, 0.f, 0.f);

        if (end > start) {
            const int c0 = start >> 6;
            const int c1 = (end - 1) >> 6;
            if (c0 == c1) {
                s  = reinterpret_cast<const float4*>(g_sums)[(b * PN + n) * D4 + tid];
                cc = reinterpret_cast<const float4*>(g_cnts)[(b * PN + n) * D4 + tid];
            } else {
                const float4* ps = reinterpret_cast<const float4*>(g_psum);
                const float4* pc = reinterpret_cast<const float4*>(g_pcnt);
                {
                    float4 a = ps[((b * NCHUNK + c0) * 2 + 1) * D4 + tid];
                    float4 d = pc[((b * NCHUNK + c0) * 2 + 1) * D4 + tid];
                    s.x += a.x; s.y += a.y; s.z += a.z; s.w += a.w;
                    cc.x += d.x; cc.y += d.y; cc.z += d.z; cc.w += d.w;
                }
                for (int cj = c0 + 1; cj <= c1; cj++) {
                    float4 a = ps[((b * NCHUNK + cj) * 2 + 0) * D4 + tid];
                    float4 d = pc[((b * NCHUNK + cj) * 2 + 0) * D4 + tid];
                    s.x += a.x; s.y += a.y; s.z += a.z; s.w += a.w;
                    cc.x += d.x; cc.y += d.y; cc.z += d.z; cc.w += d.w;
                }
            }
        }

        // block-reduce total nonzero count (for all_zero fallback)
        float tot = cc.x + cc.y + cc.z + cc.w;
        #pragma unroll
        for (int off = 16; off > 0; off >>= 1)
            tot += __shfl_down_sync(0xFFFFFFFFu, tot, off);
        __shared__ float warp_tot[6];
        const int wid = tid >> 5, lid = tid & 31;
        if (lid == 0) warp_tot[wid] = tot;
        __syncthreads();
        const float total = warp_tot[0] + warp_tot[1] + warp_tot[2] +
                            warp_tot[3] + warp_tot[4] + warp_tot[5];

        float4 mean;
        mean.x = s.x / fmaxf(cc.x, 1.f);
        mean.y = s.y / fmaxf(cc.y, 1.f);
        mean.z = s.z / fmaxf(cc.z, 1.f);
        mean.w = s.w / fmaxf(cc.w, 1.f);
        if (total == 0.f)
            mean = reinterpret_cast<const float4*>(wv)[tid];   // wv[0,0,:]

        const float lm = lmask[b * PN + n];
        float4 om;
        om.x = mean.x * lm; om.y = mean.y * lm;
        om.z = mean.z * lm; om.w = mean.w * lm;
        reinterpret_cast<float4*>(out)[((size_t)b * (2 * PN) + PN + n) * D4 + tid] = om;
    }
}

// ---------------------------------------------------------------------------
extern "C" void kernel_launch(void* const* d_in, const int* in_sizes, int n_in,
                              void* d_out, int out_size) {
    const float* wv    = (const float*)d_in[0];  // [B,S,D] f32
    const int*   ids   = (const int*)d_in[1];    // [B,N] i32
    const float* rmask = (const float*)d_in[2];  // [B,N] f32
    const int*   lens  = (const int*)d_in[3];    // [B,N] i32
    const float* lmask = (const float*)d_in[4];  // [B,N] f32
    float* out = (float*)d_out;

    fused_kernel<<<PB * NCHUNK, 192>>>(wv, lens, ids, rmask, lmask, out);
}